// round 1
// baseline (speedup 1.0000x reference)
#include <cuda_runtime.h>
#include <cstdint>

// NoiseMixModule: out = mask*A + (1-mask)*B
//   mask[r,d] = (rank of u[r,d] within row r) >= floor(7*(1-lam[r]))
//   rank via stable double-argsort == count of elements "before" it:
//   for pair j<d: u[j] <= u[d] -> d gains a predecessor, else j does.
//
// Inputs (metadata order): noise_A [B,7] f32, noise_B [B,7] f32,
//                          lam [B] f32, u [B,7] f32. Output [B,7] f32.
// B = 4194304, divisible by 4 -> 4 rows/thread, all accesses float4.

static constexpr int ROWS_PER_THREAD = 4;   // 28 floats = 7 x float4
static constexpr int THREADS = 256;

__global__ __launch_bounds__(THREADS)
void noisemix_kernel(const float4* __restrict__ A,
                     const float4* __restrict__ B,
                     const float4* __restrict__ LAM,   // 4 lam per thread
                     const float4* __restrict__ U,
                     float4* __restrict__ OUT,
                     int n_thr)
{
    int t = blockIdx.x * blockDim.x + threadIdx.x;
    if (t >= n_thr) return;

    const long base = (long)t * 7;   // float4 index into the [B,7] arrays

    // ---- load u for 4 rows (7 x float4 = 28 floats) ----
    float u[28];
#pragma unroll
    for (int k = 0; k < 7; k++) {
        float4 v = U[base + k];
        u[4*k + 0] = v.x; u[4*k + 1] = v.y;
        u[4*k + 2] = v.z; u[4*k + 3] = v.w;
    }
    float4 lv = LAM[t];
    float lams[4] = {lv.x, lv.y, lv.z, lv.w};

    // ---- per row: ranks via 21 pairwise compares, then 28-bit select mask ----
    // element index e in [0,28): row r = e/7, dim d = e%7; bit e of maskbits.
    uint32_t maskbits = 0;
#pragma unroll
    for (int r = 0; r < 4; r++) {
        // num_zero = floor(7*(1-lam)), matching float32 reference arithmetic
        int nz = (int)floorf(7.0f * (1.0f - lams[r]));
        int cnt[7] = {0, 0, 0, 0, 0, 0, 0};
        const float* ur = &u[r * 7];
#pragma unroll
        for (int j = 0; j < 7; j++) {
#pragma unroll
            for (int d = j + 1; d < 7; d++) {
                if (ur[j] <= ur[d]) cnt[d]++; else cnt[j]++;
            }
        }
#pragma unroll
        for (int d = 0; d < 7; d++) {
            if (cnt[d] >= nz) maskbits |= (1u << (r * 7 + d));
        }
    }

    // ---- stream A/B, blend by mask bit, store ----
#pragma unroll
    for (int k = 0; k < 7; k++) {
        float4 a = A[base + k];
        float4 b = B[base + k];
        float4 o;
        o.x = (maskbits >> (4*k + 0)) & 1u ? a.x : b.x;
        o.y = (maskbits >> (4*k + 1)) & 1u ? a.y : b.y;
        o.z = (maskbits >> (4*k + 2)) & 1u ? a.z : b.z;
        o.w = (maskbits >> (4*k + 3)) & 1u ? a.w : b.w;
        OUT[base + k] = o;
    }
}

extern "C" void kernel_launch(void* const* d_in, const int* in_sizes, int n_in,
                              void* d_out, int out_size)
{
    const float4* A   = (const float4*)d_in[0];   // noise_A [B,7]
    const float4* Bp  = (const float4*)d_in[1];   // noise_B [B,7]
    const float4* LAM = (const float4*)d_in[2];   // lam [B]
    const float4* U   = (const float4*)d_in[3];   // u [B,7]
    float4* OUT = (float4*)d_out;

    int Brows = in_sizes[2];                 // B = 4194304
    int n_thr = Brows / ROWS_PER_THREAD;     // 1048576 threads
    int blocks = (n_thr + THREADS - 1) / THREADS;

    noisemix_kernel<<<blocks, THREADS>>>(A, Bp, LAM, U, OUT, n_thr);
}

// round 2
// speedup vs baseline: 1.1707x; 1.1707x over previous
#include <cuda_runtime.h>
#include <cstdint>

// NoiseMixModule: out = mask*A + (1-mask)*B, mask from double-argsort ranks of u.
//
// R2 design: all GLOBAL traffic is perfectly coalesced.
//   phase 1: stage u (28KB) + lam (4KB) into smem via contiguous float4 loads
//   phase 2: per-row 7-bit mask via 21 stable compares -> smem byte array
//            (row = tid + j*256 -> stride-7 float LDS, conflict-free)
//   phase 3: stream A/B/out as contiguous float4; mask bit looked up in smem
//            with e/7 index math (4 elements per float4, bit = mask[row]>>dim)
//
// B = 4194304 rows, 7 dims. 1024 rows/block, 4096 blocks, 256 threads.

static constexpr int THREADS        = 256;
static constexpr int ROWS_PER_BLOCK = 1024;
static constexpr int F4_PER_BLOCK   = ROWS_PER_BLOCK * 7 / 4;  // 1792

__global__ __launch_bounds__(THREADS)
void noisemix_kernel(const float4* __restrict__ A,
                     const float4* __restrict__ B,
                     const float4* __restrict__ LAM,
                     const float4* __restrict__ U,
                     float4* __restrict__ OUT)
{
    __shared__ float         su[ROWS_PER_BLOCK * 7];   // 28 KB
    __shared__ float         slam[ROWS_PER_BLOCK];     //  4 KB
    __shared__ unsigned char smask[ROWS_PER_BLOCK];    //  1 KB

    const int  tid    = threadIdx.x;
    const long f4base = (long)blockIdx.x * F4_PER_BLOCK;

    // ---- phase 1: coalesced stage of u and lam ----
    float4* su4 = reinterpret_cast<float4*>(su);
#pragma unroll
    for (int k = 0; k < 7; k++) {
        su4[k * THREADS + tid] = U[f4base + k * THREADS + tid];
    }
    reinterpret_cast<float4*>(slam)[tid] =
        LAM[(long)blockIdx.x * (ROWS_PER_BLOCK / 4) + tid];
    __syncthreads();

    // ---- phase 2: per-row mask bits ----
    // rank[d] = #elements strictly-before d in stable argsort:
    //   pair (a<b): u[a] <= u[b] -> b gains a predecessor, else a does.
    // mask bit d = (rank[d] >= floor(7*(1-lam)))
#pragma unroll
    for (int j = 0; j < 4; j++) {
        const int row = tid + j * THREADS;           // stride-7 smem: conflict-free
        float uu[7];
#pragma unroll
        for (int d = 0; d < 7; d++) uu[d] = su[row * 7 + d];
        const int nz = (int)floorf(7.0f * (1.0f - slam[row]));
        int cnt[7] = {0, 0, 0, 0, 0, 0, 0};
#pragma unroll
        for (int a = 0; a < 7; a++)
#pragma unroll
            for (int b = a + 1; b < 7; b++) {
                if (uu[a] <= uu[b]) cnt[b]++; else cnt[a]++;
            }
        unsigned m = 0;
#pragma unroll
        for (int d = 0; d < 7; d++)
            if (cnt[d] >= nz) m |= (1u << d);
        smask[row] = (unsigned char)m;
    }
    __syncthreads();

    // ---- phase 3: contiguous A/B stream + blend ----
#pragma unroll
    for (int k = 0; k < 7; k++) {
        const long idx4 = f4base + k * THREADS + tid;
        const float4 a = A[idx4];
        const float4 b = B[idx4];

        int le  = (k * THREADS + tid) * 4;  // local element index 0..7167
        int row = le / 7;                   // const-div -> mul-hi
        int d   = le - row * 7;

        float4 o;
        o.x = ((smask[row] >> d) & 1) ? a.x : b.x;
        d++; if (d == 7) { d = 0; row++; }
        o.y = ((smask[row] >> d) & 1) ? a.y : b.y;
        d++; if (d == 7) { d = 0; row++; }
        o.z = ((smask[row] >> d) & 1) ? a.z : b.z;
        d++; if (d == 7) { d = 0; row++; }
        o.w = ((smask[row] >> d) & 1) ? a.w : b.w;

        OUT[idx4] = o;
    }
}

extern "C" void kernel_launch(void* const* d_in, const int* in_sizes, int n_in,
                              void* d_out, int out_size)
{
    const float4* A   = (const float4*)d_in[0];   // noise_A [B,7]
    const float4* Bp  = (const float4*)d_in[1];   // noise_B [B,7]
    const float4* LAM = (const float4*)d_in[2];   // lam [B]
    const float4* U   = (const float4*)d_in[3];   // u [B,7]
    float4* OUT = (float4*)d_out;

    const int Brows  = in_sizes[2];                    // 4194304
    const int blocks = Brows / ROWS_PER_BLOCK;         // 4096

    noisemix_kernel<<<blocks, THREADS>>>(A, Bp, LAM, U, OUT);
}

// round 3
// speedup vs baseline: 1.1845x; 1.0118x over previous
#include <cuda_runtime.h>
#include <cstdint>

// NoiseMixModule: out = mask*A + (1-mask)*B, mask from double-argsort ranks of u.
//
// R3: warp-autonomous tiles. Each warp owns 128 rows (= 224 float4 per array):
//   phase 1: stage u slice (+lam) into this warp's smem strip, coalesced float4
//   phase 2: 4 rows/lane -> 7-bit mask via 21 stable compares -> smem bytes
//   phase 3: stream A/B/out contiguously, blending via smem mask lookup
// Only __syncwarp between phases -> no block-wide bubbles; 48 resident warps
// keep the HBM pipe full. Streaming cache hints (no data reuse).
//
// B = 4194304 rows. 8 warps/block -> 1024 rows/block, 4096 blocks.

static constexpr int THREADS        = 256;
static constexpr int WARPS          = THREADS / 32;
static constexpr int ROWS_PER_WARP  = 128;
static constexpr int F4_PER_WARP    = ROWS_PER_WARP * 7 / 4;   // 224
static constexpr int ROWS_PER_BLOCK = ROWS_PER_WARP * WARPS;   // 1024
static constexpr int F4_PER_BLOCK   = F4_PER_WARP * WARPS;     // 1792

__global__ __launch_bounds__(THREADS)
void noisemix_kernel(const float4* __restrict__ A,
                     const float4* __restrict__ B,
                     const float4* __restrict__ LAM,
                     const float4* __restrict__ U,
                     float4* __restrict__ OUT)
{
    __shared__ float         su[ROWS_PER_BLOCK * 7];   // 28 KB, per-warp strips
    __shared__ float         slam[ROWS_PER_BLOCK];     //  4 KB
    __shared__ unsigned char smask[ROWS_PER_BLOCK];    //  1 KB

    const int warp = threadIdx.x >> 5;
    const int lane = threadIdx.x & 31;

    // this warp's slices
    float*         suw    = su    + warp * ROWS_PER_WARP * 7;
    float*         slamw  = slam  + warp * ROWS_PER_WARP;
    unsigned char* smaskw = smask + warp * ROWS_PER_WARP;

    const long wbase4 = (long)blockIdx.x * F4_PER_BLOCK + warp * F4_PER_WARP;

    // ---- phase 1: coalesced stage of this warp's u + lam ----
    float4* suw4 = reinterpret_cast<float4*>(suw);
#pragma unroll
    for (int k = 0; k < 7; k++) {
        suw4[k * 32 + lane] = __ldcs(&U[wbase4 + k * 32 + lane]);
    }
    reinterpret_cast<float4*>(slamw)[lane] =
        __ldcs(&LAM[(long)blockIdx.x * (ROWS_PER_BLOCK / 4)
                    + warp * (ROWS_PER_WARP / 4) + lane]);
    __syncwarp();

    // ---- phase 2: per-row mask bits (4 rows per lane) ----
    // stable double-argsort rank: pair (a<b): u[a] <= u[b] -> b gains a
    // predecessor, else a does. mask bit d = (rank[d] >= floor(7*(1-lam)))
#pragma unroll
    for (int j = 0; j < 4; j++) {
        const int row = lane + j * 32;          // stride-7 LDS: conflict-free
        float uu[7];
#pragma unroll
        for (int d = 0; d < 7; d++) uu[d] = suw[row * 7 + d];
        const int nz = (int)floorf(7.0f * (1.0f - slamw[row]));
        int cnt[7] = {0, 0, 0, 0, 0, 0, 0};
#pragma unroll
        for (int a = 0; a < 7; a++)
#pragma unroll
            for (int b = a + 1; b < 7; b++) {
                if (uu[a] <= uu[b]) cnt[b]++; else cnt[a]++;
            }
        unsigned m = 0;
#pragma unroll
        for (int d = 0; d < 7; d++)
            if (cnt[d] >= nz) m |= (1u << d);
        smaskw[row] = (unsigned char)m;
    }
    __syncwarp();

    // ---- phase 3: contiguous A/B stream + blend ----
#pragma unroll
    for (int k = 0; k < 7; k++) {
        const long idx4 = wbase4 + k * 32 + lane;
        const float4 a = __ldcs(&A[idx4]);
        const float4 b = __ldcs(&B[idx4]);

        int le  = (k * 32 + lane) * 4;    // element index within warp tile, 0..895
        int row = le / 7;                 // 0..127, const-div -> mul-hi
        int d   = le - row * 7;

        float4 o;
        o.x = ((smaskw[row] >> d) & 1) ? a.x : b.x;
        d++; if (d == 7) { d = 0; row++; }
        o.y = ((smaskw[row] >> d) & 1) ? a.y : b.y;
        d++; if (d == 7) { d = 0; row++; }
        o.z = ((smaskw[row] >> d) & 1) ? a.z : b.z;
        d++; if (d == 7) { d = 0; row++; }
        o.w = ((smaskw[row] >> d) & 1) ? a.w : b.w;

        __stcs(&OUT[idx4], o);
    }
}

extern "C" void kernel_launch(void* const* d_in, const int* in_sizes, int n_in,
                              void* d_out, int out_size)
{
    const float4* A   = (const float4*)d_in[0];   // noise_A [B,7]
    const float4* Bp  = (const float4*)d_in[1];   // noise_B [B,7]
    const float4* LAM = (const float4*)d_in[2];   // lam [B]
    const float4* U   = (const float4*)d_in[3];   // u [B,7]
    float4* OUT = (float4*)d_out;

    const int Brows  = in_sizes[2];                // 4194304
    const int blocks = Brows / ROWS_PER_BLOCK;     // 4096

    noisemix_kernel<<<blocks, THREADS>>>(A, Bp, LAM, U, OUT);
}

// round 4
// speedup vs baseline: 1.3765x; 1.1620x over previous
#include <cuda_runtime.h>
#include <cstdint>

// NoiseMixModule: out = mask*A + (1-mask)*B, mask from double-argsort ranks of u.
//
// R4: maximize in-flight memory per warp.
//   phase 1: stage u slice into this warp's smem strip (coalesced float4)
//   phase 2: 4 rows/lane; SWAR nibble counts (all 7 ranks in one u32);
//            nz from a direct coalesced scalar lam load;
//            store acc + (8-nz)*0x01111111 -> bit (4d+3) == mask bit d
//   phase 3: blend in two batched groups (4 then 3 k's): all A/B loads of a
//            group issue before any blend/store -> MLP_p1 = 8.
// No cache hints (measured slightly worse). Warp-local sync only.
//
// B = 4194304 rows. 128 rows/warp, 8 warps/block -> 1024 rows, 4096 blocks.

static constexpr int THREADS        = 256;
static constexpr int WARPS          = THREADS / 32;
static constexpr int ROWS_PER_WARP  = 128;
static constexpr int F4_PER_WARP    = ROWS_PER_WARP * 7 / 4;   // 224
static constexpr int ROWS_PER_BLOCK = ROWS_PER_WARP * WARPS;   // 1024
static constexpr int F4_PER_BLOCK   = F4_PER_WARP * WARPS;     // 1792

__global__ __launch_bounds__(THREADS)
void noisemix_kernel(const float4* __restrict__ A,
                     const float4* __restrict__ B,
                     const float*  __restrict__ LAM,
                     const float4* __restrict__ U,
                     float4* __restrict__ OUT)
{
    __shared__ float    su[ROWS_PER_BLOCK * 7];     // 28 KB, per-warp strips
    __shared__ uint32_t smask[ROWS_PER_BLOCK];      //  4 KB, SWAR mask words

    const int warp = threadIdx.x >> 5;
    const int lane = threadIdx.x & 31;

    float*    suw    = su    + warp * ROWS_PER_WARP * 7;
    uint32_t* smaskw = smask + warp * ROWS_PER_WARP;

    const long wbase4   = (long)blockIdx.x * F4_PER_BLOCK + warp * F4_PER_WARP;
    const long wrowbase = (long)blockIdx.x * ROWS_PER_BLOCK + warp * ROWS_PER_WARP;

    // ---- phase 1: coalesced stage of this warp's u ----
    float4* suw4 = reinterpret_cast<float4*>(suw);
#pragma unroll
    for (int k = 0; k < 7; k++) {
        suw4[k * 32 + lane] = U[wbase4 + k * 32 + lane];
    }
    __syncwarp();

    // ---- phase 2: SWAR rank counts, 4 rows per lane ----
    // stable double-argsort rank: pair (a<b): u[a] <= u[b] -> b gains a
    // predecessor, else a does. cnt_d lives in nibble d of acc.
    // mask bit d = (cnt_d >= nz) = bit3 of nibble d of acc + (8-nz)*0x01111111.
#pragma unroll
    for (int j = 0; j < 4; j++) {
        const int row = lane + j * 32;           // stride-7 LDS: conflict-free
        float uu[7];
#pragma unroll
        for (int d = 0; d < 7; d++) uu[d] = suw[row * 7 + d];

        const float lamv = LAM[wrowbase + row];  // coalesced 4B/lane
        const int   nz   = (int)floorf(7.0f * (1.0f - lamv));

        uint32_t acc = 0;
#pragma unroll
        for (int a = 0; a < 7; a++)
#pragma unroll
            for (int b = a + 1; b < 7; b++)
                acc += (uu[a] <= uu[b]) ? (1u << (4 * b)) : (1u << (4 * a));

        smaskw[row] = acc + (uint32_t)(8 - nz) * 0x01111111u;
    }
    __syncwarp();

    // ---- phase 3: batched A/B stream + blend ----
    // group 1: k = 0..3 (8 float4 in flight), group 2: k = 4..6 (6 float4)
#pragma unroll
    for (int g = 0; g < 2; g++) {
        const int k0 = (g == 0) ? 0 : 4;
        const int kn = (g == 0) ? 4 : 3;

        float4 a[4], b[4];
#pragma unroll
        for (int k = 0; k < 4; k++) {
            if (k < kn) {
                const long idx4 = wbase4 + (k0 + k) * 32 + lane;
                a[k] = A[idx4];
                b[k] = B[idx4];
            }
        }

#pragma unroll
        for (int k = 0; k < 4; k++) {
            if (k < kn) {
                int le  = ((k0 + k) * 32 + lane) * 4;   // element idx in warp tile
                int row = le / 7;
                int d   = le - row * 7;

                uint32_t m = smaskw[row];
                float4 o;
                o.x = (m >> (4 * d + 3)) & 1u ? a[k].x : b[k].x;
                d++; if (d == 7) { d = 0; row++; m = smaskw[row]; }
                o.y = (m >> (4 * d + 3)) & 1u ? a[k].y : b[k].y;
                d++; if (d == 7) { d = 0; row++; m = smaskw[row]; }
                o.z = (m >> (4 * d + 3)) & 1u ? a[k].z : b[k].z;
                d++; if (d == 7) { d = 0; row++; m = smaskw[row]; }
                o.w = (m >> (4 * d + 3)) & 1u ? a[k].w : b[k].w;

                OUT[wbase4 + (k0 + k) * 32 + lane] = o;
            }
        }
    }
}

extern "C" void kernel_launch(void* const* d_in, const int* in_sizes, int n_in,
                              void* d_out, int out_size)
{
    const float4* A   = (const float4*)d_in[0];   // noise_A [B,7]
    const float4* Bp  = (const float4*)d_in[1];   // noise_B [B,7]
    const float*  LAM = (const float*)d_in[2];    // lam [B]
    const float4* U   = (const float4*)d_in[3];   // u [B,7]
    float4* OUT = (float4*)d_out;

    const int Brows  = in_sizes[2];                // 4194304
    const int blocks = Brows / ROWS_PER_BLOCK;     // 4096

    noisemix_kernel<<<blocks, THREADS>>>(A, Bp, LAM, U, OUT);
}